// round 1
// baseline (speedup 1.0000x reference)
#include <cuda_runtime.h>

// ---------------------------------------------------------------------------
// SemanticLSTM: B=256, T=80, E=512, I=H=1024, L=300, F=2048, V=32000
//
// base = (emb@Wa * sem@Wb)@Wc + (cnn@Ca * sem@Cb)@Cc + bias      (B,4,H)
// SH   = sem@Ub                                                   (B,4,I)
// loop t=0..79:
//   X   = (h@Ua) * SH                                             (B,4,I)
//   pre = X@Uc + base                                             (B,4,H)
//   i,f,o = sigmoid(pre[:,0..2]);  g = tanh(pre[:,3])
//   c = f*c + i*g;  h = o*tanh(c)
// output: h (B,H) fp32
// ---------------------------------------------------------------------------

#define BB 256
#define TT 80
#define EE 512
#define II 1024
#define HH 1024
#define LL 300
#define FF 2048

// scratch (device globals; no allocation allowed)
__device__ float g_emb [BB * EE];
__device__ float g_bufA[BB * 4 * II];
__device__ float g_bufB[BB * 4 * II];
__device__ float g_base[BB * 4 * HH];
__device__ float g_SH  [BB * 4 * II];
__device__ float g_X   [BB * 4 * II];
__device__ float g_pre [BB * 4 * HH];
__device__ float g_h   [BB * HH];
__device__ float g_c   [BB * HH];

// ---------------------------------------------------------------------------
// zero h / c
// ---------------------------------------------------------------------------
__global__ __launch_bounds__(256) void zero_hc_kernel() {
    int idx = blockIdx.x * 256 + threadIdx.x;
    if (idx < BB * HH) { g_h[idx] = 0.f; g_c[idx] = 0.f; }
}

// ---------------------------------------------------------------------------
// gather emb = embed[captions[:,0]]
// Robust to captions being int64 (as declared) or int32 (jax x64 disabled):
// for int64 data the odd 32-bit words of the first 16 elements are all zero
// (values < 32000); for int32 they are random caption ids (P(all 0) ~ 0).
// ---------------------------------------------------------------------------
__global__ __launch_bounds__(256) void gather_emb_kernel(const void* __restrict__ caps,
                                                         const float* __restrict__ embed) {
    __shared__ int is64;
    if (threadIdx.x == 0) {
        const int* p = (const int*)caps;
        int z = 1;
        for (int k = 0; k < 16; k++)
            if (p[2 * k + 1] != 0) z = 0;
        is64 = z;
    }
    __syncthreads();
    int idx = blockIdx.x * 256 + threadIdx.x;   // over B*E/4
    if (idx >= BB * (EE / 4)) return;
    int b  = idx / (EE / 4);
    int e4 = idx % (EE / 4);
    long long cap;
    if (is64) cap = ((const long long*)caps)[(long long)b * TT];
    else      cap = (long long)((const int*)caps)[b * TT];
    float4 v = ((const float4*)embed)[cap * (EE / 4) + e4];
    ((float4*)g_emb)[idx] = v;
}

// ---------------------------------------------------------------------------
// Gated SGEMM: for gate g = blockIdx.z in [0,4):
//   C[b, g, n] = epilogue( sum_k A[b, g*agoff + k] * W[g, k, n] )
// A: row-major, row stride lda, per-gate column offset agoff
// W: (4, K, 1024) row-major
// C/Z: (B, 4, 1024), stride 4096 per row
// mode 0: C = acc
// mode 1: C = acc * Z
// mode 2: C = acc + Z (+ bias[g,n] if bias != nullptr)
// Tile: BM=64 x BN=128, BK=16, 256 threads, 4x8 per thread. Grid (8,4,4)=128 CTAs.
// ---------------------------------------------------------------------------
#define BM 64
#define BN 128
#define BK 16

__global__ __launch_bounds__(256) void gemm4_kernel(
    const float* __restrict__ A, int lda, int agoff,
    const float* __restrict__ W, int K,
    const float* Z, const float* __restrict__ bias,
    float* C, int mode)
{
    const int N = 1024;
    const int g  = blockIdx.z;
    const int bx = blockIdx.x;   // N tile
    const int by = blockIdx.y;   // M tile

    __shared__ float As[BK][BM];
    __shared__ float Bs[BK][BN];

    const int tid = threadIdx.x;
    const int tx  = tid & 15;    // 0..15 -> 8 cols each
    const int ty  = tid >> 4;    // 0..15 -> 4 rows each

    const float* Ag = A + (size_t)g * agoff;
    const float* Wg = W + (size_t)g * K * N + bx * BN;

    float acc[4][8];
#pragma unroll
    for (int i = 0; i < 4; i++)
#pragma unroll
        for (int j = 0; j < 8; j++) acc[i][j] = 0.f;

    const int arow = tid >> 2;          // 0..63
    const int ac   = (tid & 3) * 4;     // 0,4,8,12

    for (int kk = 0; kk < K; kk += BK) {
        // load A tile (transposed into As[k][m]) with K-bounds guard
        {
            const int m = by * BM + arow;
            const float* ap = Ag + (size_t)m * lda + kk + ac;
#pragma unroll
            for (int j = 0; j < 4; j++) {
                float v = (kk + ac + j < K) ? ap[j] : 0.f;
                As[ac + j][arow] = v;
            }
        }
        // load W tile (2 x float4 per thread) with K-bounds guard
#pragma unroll
        for (int r = 0; r < 2; r++) {
            int idx  = tid + r * 256;
            int brow = idx >> 5;          // 0..15
            int bc   = (idx & 31) * 4;    // 0..124
            int kg   = kk + brow;
            float4 v;
            if (kg < K) v = *(const float4*)(Wg + (size_t)kg * N + bc);
            else        v = make_float4(0.f, 0.f, 0.f, 0.f);
            *(float4*)&Bs[brow][bc] = v;
        }
        __syncthreads();

#pragma unroll
        for (int k = 0; k < BK; k++) {
            float4 av = *(const float4*)&As[k][ty * 4];
            float4 b0 = *(const float4*)&Bs[k][tx * 8];
            float4 b1 = *(const float4*)&Bs[k][tx * 8 + 4];
            float a[4] = {av.x, av.y, av.z, av.w};
            float b[8] = {b0.x, b0.y, b0.z, b0.w, b1.x, b1.y, b1.z, b1.w};
#pragma unroll
            for (int i = 0; i < 4; i++)
#pragma unroll
                for (int j = 0; j < 8; j++)
                    acc[i][j] = fmaf(a[i], b[j], acc[i][j]);
        }
        __syncthreads();
    }

    // epilogue
#pragma unroll
    for (int i = 0; i < 4; i++) {
        const int m = by * BM + ty * 4 + i;
        const int n0 = bx * BN + tx * 8;
        size_t row = (size_t)m * 4096 + (size_t)g * 1024 + n0;
#pragma unroll
        for (int j = 0; j < 8; j++) {
            float v = acc[i][j];
            if (mode == 1)      v *= Z[row + j];
            else if (mode == 2) {
                v += Z[row + j];
                if (bias) v += bias[g * 1024 + n0 + j];
            }
            C[row + j] = v;
        }
    }
}

// ---------------------------------------------------------------------------
// LSTM gate update from g_pre (B,4,H)
// ---------------------------------------------------------------------------
__global__ __launch_bounds__(256) void lstm_gate_kernel(float* out) {
    int idx = blockIdx.x * 256 + threadIdx.x;
    if (idx >= BB * HH) return;
    int b  = idx >> 10;
    int hh = idx & 1023;
    const float* p = g_pre + ((size_t)b << 12) + hh;
    float xi = p[0], xf = p[1024], xo = p[2048], xg = p[3072];
    float ig = 1.f / (1.f + expf(-xi));
    float fg = 1.f / (1.f + expf(-xf));
    float og = 1.f / (1.f + expf(-xo));
    float gg = tanhf(xg);
    float c = fg * g_c[idx] + ig * gg;
    float h = og * tanhf(c);
    g_c[idx] = c;
    g_h[idx] = h;
    if (out) out[idx] = h;
}

// ---------------------------------------------------------------------------
extern "C" void kernel_launch(void* const* d_in, const int* in_sizes, int n_in,
                              void* d_out, int out_size) {
    const void*  caps  = d_in[0];
    const float* cnn   = (const float*)d_in[1];
    const float* sem   = (const float*)d_in[2];
    const float* embed = (const float*)d_in[3];
    const float* Wa    = (const float*)d_in[4];
    const float* Wb    = (const float*)d_in[5];
    const float* Wc    = (const float*)d_in[6];
    const float* Ua    = (const float*)d_in[7];
    const float* Ub    = (const float*)d_in[8];
    const float* Uc    = (const float*)d_in[9];
    const float* Ca    = (const float*)d_in[10];
    const float* Cb    = (const float*)d_in[11];
    const float* Cc    = (const float*)d_in[12];
    const float* bias  = (const float*)d_in[13];

    float *p_emb, *p_bufA, *p_bufB, *p_base, *p_SH, *p_X, *p_h;
    cudaGetSymbolAddress((void**)&p_emb,  g_emb);
    cudaGetSymbolAddress((void**)&p_bufA, g_bufA);
    cudaGetSymbolAddress((void**)&p_bufB, g_bufB);
    cudaGetSymbolAddress((void**)&p_base, g_base);
    cudaGetSymbolAddress((void**)&p_SH,   g_SH);
    cudaGetSymbolAddress((void**)&p_X,    g_X);
    cudaGetSymbolAddress((void**)&p_h,    g_h);
    float* p_pre; cudaGetSymbolAddress((void**)&p_pre, g_pre);

    dim3 gg(1024 / BN, BB / BM, 4);   // (8,4,4) = 128 CTAs

    zero_hc_kernel<<<(BB * HH + 255) / 256, 256>>>();
    gather_emb_kernel<<<(BB * EE / 4 + 255) / 256, 256>>>(caps, embed);

    // base = (emb@Wa * sem@Wb)@Wc + (cnn@Ca * sem@Cb)@Cc + bias
    gemm4_kernel<<<gg, 256>>>(p_emb,  EE,   0,    Wa, EE, nullptr, nullptr, p_bufA, 0);
    gemm4_kernel<<<gg, 256>>>(sem,    LL,   0,    Wb, LL, p_bufA,  nullptr, p_bufB, 1);
    gemm4_kernel<<<gg, 256>>>(p_bufB, 4096, 1024, Wc, II, nullptr, nullptr, p_base, 0);
    gemm4_kernel<<<gg, 256>>>(cnn,    FF,   0,    Ca, FF, nullptr, nullptr, p_bufA, 0);
    gemm4_kernel<<<gg, 256>>>(sem,    LL,   0,    Cb, LL, p_bufA,  nullptr, p_bufB, 1);
    gemm4_kernel<<<gg, 256>>>(p_bufB, 4096, 1024, Cc, II, p_base,  bias,    p_base, 2);
    // SH = sem@Ub
    gemm4_kernel<<<gg, 256>>>(sem,    LL,   0,    Ub, LL, nullptr, nullptr, p_SH,   0);

    for (int t = 0; t < TT; t++) {
        gemm4_kernel<<<gg, 256>>>(p_h, HH,   0,    Ua, HH, p_SH,   nullptr, p_X,   1);
        gemm4_kernel<<<gg, 256>>>(p_X, 4096, 1024, Uc, II, p_base, nullptr, p_pre, 2);
        lstm_gate_kernel<<<(BB * HH + 255) / 256, 256>>>(t == TT - 1 ? (float*)d_out : nullptr);
    }
}

// round 3
// speedup vs baseline: 3.4485x; 3.4485x over previous
#include <cuda_runtime.h>
#include <cuda_bf16.h>
#include <cstdint>

// ---------------------------------------------------------------------------
// SemanticLSTM: B=256, T=80, E=512, I=H=1024, L=300, F=2048, V=32000
// Recurrence GEMMs on tensor cores via base-ISA mma.sync bf16 (sm_103 target
// has no tcgen05), with bf16x3 split: hi*hi + hi*lo + lo*hi, fp32 accum.
// ---------------------------------------------------------------------------

#define BB 256
#define TT 80
#define EE 512
#define II 1024
#define HH 1024
#define LL 300
#define FF 2048

// fp32 scratch
__device__ float g_emb [BB * EE];
__device__ float g_bufA[BB * 4 * II];
__device__ float g_bufB[BB * 4 * II];
__device__ float g_base[BB * 4 * HH];
__device__ float g_SH  [BB * 4 * II];
__device__ float g_pre [BB * 4 * HH];
__device__ float g_c   [BB * HH];

// bf16 split buffers
__device__ __nv_bfloat16 g_hH[BB * HH];
__device__ __nv_bfloat16 g_hL[BB * HH];
__device__ __nv_bfloat16 g_xH[BB * 4 * II];
__device__ __nv_bfloat16 g_xL[BB * 4 * II];
// transposed split weights: UaT[g,i,h] = Ua[g,h,i]; UcT[g,h,i] = Uc[g,i,h]
__device__ __nv_bfloat16 g_UaT_h[4 * 1024 * 1024];
__device__ __nv_bfloat16 g_UaT_l[4 * 1024 * 1024];
__device__ __nv_bfloat16 g_UcT_h[4 * 1024 * 1024];
__device__ __nv_bfloat16 g_UcT_l[4 * 1024 * 1024];

// ---------------------------------------------------------------------------
// helpers (all base-ISA: cp.async sm_80+, ldmatrix sm_75+, mma.sync sm_80+)
// ---------------------------------------------------------------------------
__device__ __forceinline__ uint32_t smem_u32(const void* p) {
    uint32_t a;
    asm("{ .reg .u64 t; cvta.to.shared.u64 t, %1; cvt.u32.u64 %0, t; }" : "=r"(a) : "l"(p));
    return a;
}
__device__ __forceinline__ void cpa16(uint32_t d, const void* s) {
    asm volatile("cp.async.cg.shared.global [%0], [%1], 16;" :: "r"(d), "l"(s));
}
__device__ __forceinline__ void cpa_commit() { asm volatile("cp.async.commit_group;"); }
template <int N>
__device__ __forceinline__ void cpa_wait() {
    asm volatile("cp.async.wait_group %0;" :: "n"(N) : "memory");
}
__device__ __forceinline__ void ldm_x4(uint32_t* r, uint32_t a) {
    asm volatile("ldmatrix.sync.aligned.m8n8.x4.shared.b16 {%0,%1,%2,%3}, [%4];"
                 : "=r"(r[0]), "=r"(r[1]), "=r"(r[2]), "=r"(r[3]) : "r"(a));
}
__device__ __forceinline__ void mma16816(float* d, const uint32_t* a, uint32_t b0, uint32_t b1) {
    asm volatile(
        "mma.sync.aligned.m16n8k16.row.col.f32.bf16.bf16.f32 "
        "{%0,%1,%2,%3},{%4,%5,%6,%7},{%8,%9},{%0,%1,%2,%3};"
        : "+f"(d[0]), "+f"(d[1]), "+f"(d[2]), "+f"(d[3])
        : "r"(a[0]), "r"(a[1]), "r"(a[2]), "r"(a[3]), "r"(b0), "r"(b1));
}

// ---------------------------------------------------------------------------
// zero state
// ---------------------------------------------------------------------------
__global__ __launch_bounds__(256) void zero_hc_kernel() {
    int idx = blockIdx.x * 256 + threadIdx.x;
    if (idx < BB * HH) {
        g_c[idx] = 0.f;
        g_hH[idx] = __float2bfloat16(0.f);
        g_hL[idx] = __float2bfloat16(0.f);
    }
}

// ---------------------------------------------------------------------------
// gather emb = embed[captions[:,0]]  (int64/int32 robust)
// ---------------------------------------------------------------------------
__global__ __launch_bounds__(256) void gather_emb_kernel(const void* __restrict__ caps,
                                                         const float* __restrict__ embed) {
    __shared__ int is64;
    if (threadIdx.x == 0) {
        const int* p = (const int*)caps;
        int z = 1;
        for (int k = 0; k < 16; k++)
            if (p[2 * k + 1] != 0) z = 0;
        is64 = z;
    }
    __syncthreads();
    int idx = blockIdx.x * 256 + threadIdx.x;
    if (idx >= BB * (EE / 4)) return;
    int b  = idx / (EE / 4);
    int e4 = idx % (EE / 4);
    long long cap;
    if (is64) cap = ((const long long*)caps)[(long long)b * TT];
    else      cap = (long long)((const int*)caps)[b * TT];
    float4 v = ((const float4*)embed)[cap * (EE / 4) + e4];
    ((float4*)g_emb)[idx] = v;
}

// ---------------------------------------------------------------------------
// transpose + bf16 split: dst[g,a,b] = split(src[g,b,a]); grid (32,32,4)
// ---------------------------------------------------------------------------
__global__ __launch_bounds__(256) void convT_kernel(const float* __restrict__ src,
                                                    __nv_bfloat16* __restrict__ dh,
                                                    __nv_bfloat16* __restrict__ dl) {
    __shared__ float t[32][33];
    int g  = blockIdx.z;
    int x0 = blockIdx.x * 32;
    int y0 = blockIdx.y * 32;
    int tx = threadIdx.x & 31, ty = threadIdx.x >> 5;
    const float* s = src + (size_t)g * 1048576;
#pragma unroll
    for (int k = 0; k < 4; k++)
        t[ty + k * 8][tx] = s[(size_t)(y0 + ty + k * 8) * 1024 + x0 + tx];
    __syncthreads();
    __nv_bfloat16* oh = dh + (size_t)g * 1048576;
    __nv_bfloat16* ol = dl + (size_t)g * 1048576;
#pragma unroll
    for (int k = 0; k < 4; k++) {
        float v = t[tx][ty + k * 8];
        size_t o = (size_t)(x0 + ty + k * 8) * 1024 + y0 + tx;
        __nv_bfloat16 hi = __float2bfloat16(v);
        oh[o] = hi;
        ol[o] = __float2bfloat16(v - __bfloat162float(hi));
    }
}

// ---------------------------------------------------------------------------
// fp32 prologue SGEMM (7 launches only)
// ---------------------------------------------------------------------------
#define BM 64
#define BN 128
#define BK 16

__global__ __launch_bounds__(256) void gemm4_kernel(
    const float* __restrict__ A, int lda, int agoff,
    const float* __restrict__ W, int K,
    const float* Z, const float* __restrict__ bias,
    float* C, int mode)
{
    const int N = 1024;
    const int g  = blockIdx.z;
    const int bx = blockIdx.x;
    const int by = blockIdx.y;

    __shared__ float As[BK][BM];
    __shared__ float Bs[BK][BN];

    const int tid = threadIdx.x;
    const int tx  = tid & 15;
    const int ty  = tid >> 4;

    const float* Ag = A + (size_t)g * agoff;
    const float* Wg = W + (size_t)g * K * N + bx * BN;

    float acc[4][8];
#pragma unroll
    for (int i = 0; i < 4; i++)
#pragma unroll
        for (int j = 0; j < 8; j++) acc[i][j] = 0.f;

    const int arow = tid >> 2;
    const int ac   = (tid & 3) * 4;

    for (int kk = 0; kk < K; kk += BK) {
        {
            const int m = by * BM + arow;
            const float* ap = Ag + (size_t)m * lda + kk + ac;
#pragma unroll
            for (int j = 0; j < 4; j++) {
                float v = (kk + ac + j < K) ? ap[j] : 0.f;
                As[ac + j][arow] = v;
            }
        }
#pragma unroll
        for (int r = 0; r < 2; r++) {
            int idx  = tid + r * 256;
            int brow = idx >> 5;
            int bc   = (idx & 31) * 4;
            int kg   = kk + brow;
            float4 v;
            if (kg < K) v = *(const float4*)(Wg + (size_t)kg * N + bc);
            else        v = make_float4(0.f, 0.f, 0.f, 0.f);
            *(float4*)&Bs[brow][bc] = v;
        }
        __syncthreads();

#pragma unroll
        for (int k = 0; k < BK; k++) {
            float4 av = *(const float4*)&As[k][ty * 4];
            float4 b0 = *(const float4*)&Bs[k][tx * 8];
            float4 b1 = *(const float4*)&Bs[k][tx * 8 + 4];
            float a[4] = {av.x, av.y, av.z, av.w};
            float b[8] = {b0.x, b0.y, b0.z, b0.w, b1.x, b1.y, b1.z, b1.w};
#pragma unroll
            for (int i = 0; i < 4; i++)
#pragma unroll
                for (int j = 0; j < 8; j++)
                    acc[i][j] = fmaf(a[i], b[j], acc[i][j]);
        }
        __syncthreads();
    }

#pragma unroll
    for (int i = 0; i < 4; i++) {
        const int m = by * BM + ty * 4 + i;
        const int n0 = bx * BN + tx * 8;
        size_t row = (size_t)m * 4096 + (size_t)g * 1024 + n0;
#pragma unroll
        for (int j = 0; j < 8; j++) {
            float v = acc[i][j];
            if (mode == 1)      v *= Z[row + j];
            else if (mode == 2) {
                v += Z[row + j];
                if (bias) v += bias[g * 1024 + n0 + j];
            }
            C[row + j] = v;
        }
    }
}

// ---------------------------------------------------------------------------
// Tensor-core bf16x3 GEMM via mma.sync.m16n8k16.
// CTA tile M=64 x N=128, BK=64, K=1024 (16 chunks), double-buffered cp.async.
// grid (8 n-tiles, 4 m-tiles, 4 gates) = 128 CTAs, 256 threads (8 warps 32x32).
// Smem rows padded to 144B (72 bf16) -> conflict-free ldmatrix & cp.async.
// mode 1: out = D * Z -> bf16 hi/lo ; mode 2: out = D + Z -> fp32
// ---------------------------------------------------------------------------
#define ASTRIDE  144                     // bytes per smem row (64 bf16 + pad)
#define A_TILE_B (64  * ASTRIDE)         // 9216
#define B_TILE_B (128 * ASTRIDE)         // 18432
#define STAGE_B  (2 * (A_TILE_B + B_TILE_B))  // 55296: Ah|Al|Bh|Bl
#define MM_SMEM  (2 * STAGE_B)           // 110592

__device__ __forceinline__ void load_stage(
    uint32_t sa, uint32_t sb,
    const __nv_bfloat16* Ah, const __nv_bfloat16* Al, int lda,
    const __nv_bfloat16* Bh, const __nv_bfloat16* Bl,
    int k0, int tid)
{
#pragma unroll
    for (int r = 0; r < 2; r++) {           // A: 64 rows x 8 chunks = 512
        int id  = tid + (r << 8);
        int row = id >> 3;
        int c   = id & 7;
        uint32_t d = sa + row * ASTRIDE + c * 16;
        size_t   s = (size_t)row * lda + k0 + c * 8;
        cpa16(d,           Ah + s);
        cpa16(d + A_TILE_B, Al + s);
    }
#pragma unroll
    for (int r = 0; r < 4; r++) {           // B: 128 rows x 8 chunks = 1024
        int id  = tid + (r << 8);
        int row = id >> 3;
        int c   = id & 7;
        uint32_t d = sb + row * ASTRIDE + c * 16;
        size_t   s = (size_t)row * 1024 + k0 + c * 8;
        cpa16(d,           Bh + s);
        cpa16(d + B_TILE_B, Bl + s);
    }
}

__global__ __launch_bounds__(256, 1) void tcmma_kernel(
    const __nv_bfloat16* __restrict__ Ah, const __nv_bfloat16* __restrict__ Al,
    int lda, int agoff,
    const __nv_bfloat16* __restrict__ Bh, const __nv_bfloat16* __restrict__ Bl,
    const float* __restrict__ Z,
    float* outF, __nv_bfloat16* outH, __nv_bfloat16* outL, int mode)
{
    extern __shared__ char dsm[];
    const uint32_t sbase = smem_u32(dsm);

    const int g    = blockIdx.z;
    const int nx   = blockIdx.x;   // 0..7 (128-wide n tile within gate)
    const int my   = blockIdx.y;   // 0..3 (64-wide m tile)
    const int tid  = threadIdx.x;
    const int lane = tid & 31;
    const int warp = tid >> 5;
    const int wm   = warp & 1;     // 0..1 -> 32 rows
    const int wn   = warp >> 1;    // 0..3 -> 32 cols

    const __nv_bfloat16* Ahp = Ah + (size_t)g * agoff + (size_t)(my * 64) * lda;
    const __nv_bfloat16* Alp = Al + (size_t)g * agoff + (size_t)(my * 64) * lda;
    const __nv_bfloat16* Bhp = Bh + ((size_t)g * 1024 + nx * 128) * 1024;
    const __nv_bfloat16* Blp = Bl + ((size_t)g * 1024 + nx * 128) * 1024;

    float acc[2][4][4];
#pragma unroll
    for (int i = 0; i < 2; i++)
#pragma unroll
        for (int j = 0; j < 4; j++)
#pragma unroll
            for (int k = 0; k < 4; k++) acc[i][j][k] = 0.f;

    // per-lane ldmatrix base offsets
    const int rin  = lane & 7;
    const int quad = lane >> 3;
    // A x4: regs = (m0-7,klo),(m8-15,klo),(m0-7,khi),(m8-15,khi)
    const uint32_t aoff = ((quad & 1) * 8 + rin) * ASTRIDE + (quad >> 1) * 16;
    // B x4: regs = (n0-7,klo),(n0-7,khi),(n8-15,klo),(n8-15,khi)
    const uint32_t boff = ((quad >> 1) * 8 + rin) * ASTRIDE + (quad & 1) * 16;
    const uint32_t aBase = sbase + wm * 32 * ASTRIDE + aoff;
    const uint32_t bBase = sbase + 2 * A_TILE_B + wn * 32 * ASTRIDE + boff;

    // preload chunk 0
    load_stage(sbase, sbase + 2 * A_TILE_B, Ahp, Alp, lda, Bhp, Blp, 0, tid);
    cpa_commit();

    const int NC = 16;
    for (int c = 0; c < NC; c++) {
        const uint32_t soff = (c & 1) * STAGE_B;
        if (c + 1 < NC) {
            const uint32_t s2 = ((c + 1) & 1) * STAGE_B;
            load_stage(sbase + s2, sbase + s2 + 2 * A_TILE_B,
                       Ahp, Alp, lda, Bhp, Blp, (c + 1) * 64, tid);
            cpa_commit();
            cpa_wait<1>();
        } else {
            cpa_wait<0>();
        }
        __syncthreads();

        const uint32_t aCur = aBase + soff;
        const uint32_t bCur = bBase + soff;
#pragma unroll
        for (int ks = 0; ks < 4; ks++) {
            uint32_t ah[2][4], al[2][4], bh[2][4], bl[2][4];
            const uint32_t ka = aCur + ks * 32;
            const uint32_t kb = bCur + ks * 32;
            ldm_x4(ah[0], ka);
            ldm_x4(ah[1], ka + 16 * ASTRIDE);
            ldm_x4(al[0], ka + A_TILE_B);
            ldm_x4(al[1], ka + A_TILE_B + 16 * ASTRIDE);
            ldm_x4(bh[0], kb);
            ldm_x4(bh[1], kb + 16 * ASTRIDE);
            ldm_x4(bl[0], kb + B_TILE_B);
            ldm_x4(bl[1], kb + B_TILE_B + 16 * ASTRIDE);
#pragma unroll
            for (int im = 0; im < 2; im++)
#pragma unroll
                for (int jn = 0; jn < 4; jn++) {
                    const int jp = jn >> 1, q = (jn & 1) * 2;
                    mma16816(acc[im][jn], ah[im], bh[jp][q], bh[jp][q + 1]);
                    mma16816(acc[im][jn], ah[im], bl[jp][q], bl[jp][q + 1]);
                    mma16816(acc[im][jn], al[im], bh[jp][q], bh[jp][q + 1]);
                }
        }
        __syncthreads();
    }

    // epilogue
#pragma unroll
    for (int im = 0; im < 2; im++) {
        const int m0 = my * 64 + wm * 32 + im * 16 + (lane >> 2);
#pragma unroll
        for (int jn = 0; jn < 4; jn++) {
            const int n0 = nx * 128 + wn * 32 + jn * 8 + (lane & 3) * 2;
            const size_t p0 = (size_t)m0 * 4096 + (size_t)g * 1024 + n0;
            const size_t p1 = p0 + 8 * 4096;   // m0 + 8
            const float* a = acc[im][jn];
            if (mode == 1) {
                float x0 = a[0] * Z[p0],     x1 = a[1] * Z[p0 + 1];
                float x2 = a[2] * Z[p1],     x3 = a[3] * Z[p1 + 1];
                __nv_bfloat16 h0 = __float2bfloat16(x0);
                __nv_bfloat16 h1 = __float2bfloat16(x1);
                __nv_bfloat16 h2 = __float2bfloat16(x2);
                __nv_bfloat16 h3 = __float2bfloat16(x3);
                outH[p0] = h0; outH[p0 + 1] = h1;
                outH[p1] = h2; outH[p1 + 1] = h3;
                outL[p0]     = __float2bfloat16(x0 - __bfloat162float(h0));
                outL[p0 + 1] = __float2bfloat16(x1 - __bfloat162float(h1));
                outL[p1]     = __float2bfloat16(x2 - __bfloat162float(h2));
                outL[p1 + 1] = __float2bfloat16(x3 - __bfloat162float(h3));
            } else {
                outF[p0]     = a[0] + Z[p0];
                outF[p0 + 1] = a[1] + Z[p0 + 1];
                outF[p1]     = a[2] + Z[p1];
                outF[p1 + 1] = a[3] + Z[p1 + 1];
            }
        }
    }
}

// ---------------------------------------------------------------------------
// LSTM gate update: reads g_pre, updates g_c, writes h as bf16 hi/lo
// ---------------------------------------------------------------------------
__global__ __launch_bounds__(256) void lstm_gate_kernel(float* out) {
    int idx = blockIdx.x * 256 + threadIdx.x;
    if (idx >= BB * HH) return;
    int b  = idx >> 10;
    int hh = idx & 1023;
    const float* p = g_pre + ((size_t)b << 12) + hh;
    float xi = p[0], xf = p[1024], xo = p[2048], xg = p[3072];
    float ig = 1.f / (1.f + expf(-xi));
    float fg = 1.f / (1.f + expf(-xf));
    float og = 1.f / (1.f + expf(-xo));
    float gg = tanhf(xg);
    float c = fg * g_c[idx] + ig * gg;
    float h = og * tanhf(c);
    g_c[idx] = c;
    __nv_bfloat16 hi = __float2bfloat16(h);
    g_hH[idx] = hi;
    g_hL[idx] = __float2bfloat16(h - __bfloat162float(hi));
    if (out) out[idx] = h;
}

// ---------------------------------------------------------------------------
extern "C" void kernel_launch(void* const* d_in, const int* in_sizes, int n_in,
                              void* d_out, int out_size) {
    const void*  caps  = d_in[0];
    const float* cnn   = (const float*)d_in[1];
    const float* sem   = (const float*)d_in[2];
    const float* embed = (const float*)d_in[3];
    const float* Wa    = (const float*)d_in[4];
    const float* Wb    = (const float*)d_in[5];
    const float* Wc    = (const float*)d_in[6];
    const float* Ua    = (const float*)d_in[7];
    const float* Ub    = (const float*)d_in[8];
    const float* Uc    = (const float*)d_in[9];
    const float* Ca    = (const float*)d_in[10];
    const float* Cb    = (const float*)d_in[11];
    const float* Cc    = (const float*)d_in[12];
    const float* bias  = (const float*)d_in[13];

    float *p_emb, *p_bufA, *p_bufB, *p_base, *p_SH, *p_pre;
    cudaGetSymbolAddress((void**)&p_emb,  g_emb);
    cudaGetSymbolAddress((void**)&p_bufA, g_bufA);
    cudaGetSymbolAddress((void**)&p_bufB, g_bufB);
    cudaGetSymbolAddress((void**)&p_base, g_base);
    cudaGetSymbolAddress((void**)&p_SH,   g_SH);
    cudaGetSymbolAddress((void**)&p_pre,  g_pre);

    __nv_bfloat16 *p_hH, *p_hL, *p_xH, *p_xL;
    __nv_bfloat16 *p_UaTh, *p_UaTl, *p_UcTh, *p_UcTl;
    cudaGetSymbolAddress((void**)&p_hH, g_hH);
    cudaGetSymbolAddress((void**)&p_hL, g_hL);
    cudaGetSymbolAddress((void**)&p_xH, g_xH);
    cudaGetSymbolAddress((void**)&p_xL, g_xL);
    cudaGetSymbolAddress((void**)&p_UaTh, g_UaT_h);
    cudaGetSymbolAddress((void**)&p_UaTl, g_UaT_l);
    cudaGetSymbolAddress((void**)&p_UcTh, g_UcT_h);
    cudaGetSymbolAddress((void**)&p_UcTl, g_UcT_l);

    cudaFuncSetAttribute(tcmma_kernel, cudaFuncAttributeMaxDynamicSharedMemorySize, MM_SMEM);

    dim3 gg(1024 / BN, BB / BM, 4);   // prologue fp32 GEMM grid
    dim3 tg(8, 4, 4);                 // tensor-core GEMM grid (128 CTAs)
    dim3 cg(32, 32, 4);               // weight conversion grid

    zero_hc_kernel<<<(BB * HH + 255) / 256, 256>>>();
    gather_emb_kernel<<<(BB * EE / 4 + 255) / 256, 256>>>(caps, embed);
    convT_kernel<<<cg, 256>>>(Ua, p_UaTh, p_UaTl);
    convT_kernel<<<cg, 256>>>(Uc, p_UcTh, p_UcTl);

    // base = (emb@Wa * sem@Wb)@Wc + (cnn@Ca * sem@Cb)@Cc + bias ; SH = sem@Ub
    gemm4_kernel<<<gg, 256>>>(p_emb,  EE,   0,    Wa, EE, nullptr, nullptr, p_bufA, 0);
    gemm4_kernel<<<gg, 256>>>(sem,    LL,   0,    Wb, LL, p_bufA,  nullptr, p_bufB, 1);
    gemm4_kernel<<<gg, 256>>>(p_bufB, 4096, 1024, Wc, II, nullptr, nullptr, p_base, 0);
    gemm4_kernel<<<gg, 256>>>(cnn,    FF,   0,    Ca, FF, nullptr, nullptr, p_bufA, 0);
    gemm4_kernel<<<gg, 256>>>(sem,    LL,   0,    Cb, LL, p_bufA,  nullptr, p_bufB, 1);
    gemm4_kernel<<<gg, 256>>>(p_bufB, 4096, 1024, Cc, II, p_base,  bias,    p_base, 2);
    gemm4_kernel<<<gg, 256>>>(sem,    LL,   0,    Ub, LL, nullptr, nullptr, p_SH,   0);

    for (int t = 0; t < TT; t++) {
        // X = (h @ Ua) * SH   -> bf16 hi/lo
        tcmma_kernel<<<tg, 256, MM_SMEM>>>(p_hH, p_hL, 1024, 0,
                                           p_UaTh, p_UaTl, p_SH,
                                           nullptr, p_xH, p_xL, 1);
        // pre = (X @ Uc) + base  -> fp32
        tcmma_kernel<<<tg, 256, MM_SMEM>>>(p_xH, p_xL, 4096, 1024,
                                           p_UcTh, p_UcTl, p_base,
                                           p_pre, nullptr, nullptr, 2);
        lstm_gate_kernel<<<(BB * HH + 255) / 256, 256>>>(t == TT - 1 ? (float*)d_out : nullptr);
    }
}